// round 11
// baseline (speedup 1.0000x reference)
#include <cuda_runtime.h>
#include <math.h>

#define BB    2
#define HH    360
#define WG    360
#define HW    (HH*WG)          // 129600
#define NCLS  10
#define NPROP 200
#define CC    128
#define NPTS  80000
#define BSHIFT 15
#define NBUCK 32768            // bucket = float_bits >> 15
#define SEL_CAP 4096

// output layout: qf (B,C,P) | query_pos (B,P,2) | qhs (B,NCLS,P) | cls (B,P)
#define OFF_QF  0
#define OFF_POS (BB*CC*NPROP)            // 51200
#define OFF_QHS (OFF_POS + BB*NPROP*2)   // 52000
#define OFF_CLS (OFF_QHS + BB*NCLS*NPROP)// 56000

typedef unsigned long long ull;

// ---------------- scratch ---------------------------------------------------
__device__ float  g_heat8[BB*HW*8];      // packed [b*HW+cell][c], classes 0..7 (zero-init)
__device__ float  g_supp8[BB*HW*8];      // packed suppressed heat, cls 0..7 (zero-init)
__device__ float2 g_supp89[NPTS];        // per-point cls 8,9 (always overwritten)
__device__ int    g_map[BB*HW];          // cell -> row; only read at occupied cells
__device__ unsigned g_hist[BB*NBUCK];
__device__ int    g_thr[BB];
__device__ int    g_selcnt[BB];
__device__ unsigned g_done;
__device__ ull    g_sel[BB*SEL_CAP];

// ---------------- packed f32x2 helpers --------------------------------------
__device__ __forceinline__ ull pk2(float lo, float hi) {
    ull r;
    asm("mov.b64 %0, {%1, %2};" : "=l"(r)
        : "r"(__float_as_uint(lo)), "r"(__float_as_uint(hi)));
    return r;
}
__device__ __forceinline__ ull pk1(float v) {
    ull r;
    asm("mov.b64 %0, {%1, %1};" : "=l"(r) : "r"(__float_as_uint(v)));
    return r;
}
__device__ __forceinline__ void upk(ull p, float& lo, float& hi) {
    unsigned a, b;
    asm("mov.b64 {%0, %1}, %2;" : "=r"(a), "=r"(b) : "l"(p));
    lo = __uint_as_float(a); hi = __uint_as_float(b);
}
__device__ __forceinline__ ull ffma2(ull a, ull b, ull c) {
    ull d;
    asm("fma.rn.f32x2 %0, %1, %2, %3;" : "=l"(d) : "l"(a), "l"(b), "l"(c));
    return d;
}
__device__ __forceinline__ float sigmf(float x) {
    return 1.f / (1.f + expf(-x));
}

// ---------------- init ------------------------------------------------------
__global__ void init_kernel() {
    int stride = gridDim.x * blockDim.x;
    int i0 = blockIdx.x * blockDim.x + threadIdx.x;
    float4 z = make_float4(0.f, 0.f, 0.f, 0.f);
    for (int j = i0; j < BB*HW*8/4; j += stride) {
        ((float4*)g_heat8)[j] = z;
        ((float4*)g_supp8)[j] = z;
    }
    uint4 zu = make_uint4(0u, 0u, 0u, 0u);
    for (int j = i0; j < BB*NBUCK/4; j += stride) ((uint4*)g_hist)[j] = zu;
    if (i0 < BB) g_selcnt[i0] = 0;
    if (i0 == 0) g_done = 0u;
}

// ---------------- fused MLP head: 625 x 128-row tiles, dup-A f32x2 ----------
// smem(floats): sW1 [0,16384) | sA2(ull,32x130) [16384,24704) |
//               sH reuse [0,16896) | sW2 [24704,25984)
#define SMEM_FLOATS 25984
__global__ void __launch_bounds__(256, 2)
gemm_kernel(const float* __restrict__ feat, const float* __restrict__ W1,
            const float* __restrict__ b1,  const float* __restrict__ W2,
            const float* __restrict__ b2,  const int* __restrict__ idxs)
{
    extern __shared__ float sm[];
    float* sW1 = sm;                        // 128*128
    ull*   sA2 = (ull*)(sm + 16384);        // 32 x 130 (dup pairs)
    float* sH  = sm;                        // 128*132 (reuses W1 region)
    float* sW2 = sm + 24704;                // 128*10

    const int tid = threadIdx.x;
    const int rowBase = blockIdx.x * 128;

    for (int i = tid*4; i < CC*CC; i += 256*4)
        *(float4*)(sW1 + i) = *(const float4*)(W1 + i);
    for (int i = tid; i < CC*NCLS; i += 256)
        sW2[i] = W2[i];

    const int tn = tid & 15, tm = tid >> 4;
    const int c0 = tn*4;
    const int c1 = 64 + tn*4;

    ull acc2[8][4];
    {
        ull p0 = pk2(b1[c0],   b1[c0+1]);
        ull p1 = pk2(b1[c0+2], b1[c0+3]);
        ull p2 = pk2(b1[c1],   b1[c1+1]);
        ull p3 = pk2(b1[c1+2], b1[c1+3]);
#pragma unroll
        for (int i = 0; i < 8; i++) {
            acc2[i][0] = p0; acc2[i][1] = p1; acc2[i][2] = p2; acc2[i][3] = p3;
        }
    }
    __syncthreads();   // W1/W2 visible

    const int lrow = tid >> 3;          // 0..31
    const int lk4  = (tid & 7) * 4;     // 0..28
    for (int kc = 0; kc < 4; kc++) {
#pragma unroll
        for (int pass = 0; pass < 4; pass++) {
            int r = lrow + pass*32;
            float4 v = *(const float4*)(feat + (size_t)(rowBase + r)*CC + kc*32 + lk4);
            sA2[(lk4+0)*130 + r] = pk1(v.x);
            sA2[(lk4+1)*130 + r] = pk1(v.y);
            sA2[(lk4+2)*130 + r] = pk1(v.z);
            sA2[(lk4+3)*130 + r] = pk1(v.w);
        }
        __syncthreads();
#pragma unroll 2
        for (int k = 0; k < 32; k++) {
            const ull* ap = sA2 + k*130 + tm*8;
            ulonglong2 A0 = *(const ulonglong2*)(ap);
            ulonglong2 A1 = *(const ulonglong2*)(ap + 2);
            ulonglong2 A2 = *(const ulonglong2*)(ap + 4);
            ulonglong2 A3 = *(const ulonglong2*)(ap + 6);
            const ull* bw = (const ull*)(sW1 + (kc*32+k)*128);
            ull w0 = bw[tn*2];
            ull w1 = bw[tn*2 + 1];
            ull w2 = bw[32 + tn*2];
            ull w3 = bw[32 + tn*2 + 1];
            acc2[0][0]=ffma2(A0.x,w0,acc2[0][0]); acc2[0][1]=ffma2(A0.x,w1,acc2[0][1]);
            acc2[0][2]=ffma2(A0.x,w2,acc2[0][2]); acc2[0][3]=ffma2(A0.x,w3,acc2[0][3]);
            acc2[1][0]=ffma2(A0.y,w0,acc2[1][0]); acc2[1][1]=ffma2(A0.y,w1,acc2[1][1]);
            acc2[1][2]=ffma2(A0.y,w2,acc2[1][2]); acc2[1][3]=ffma2(A0.y,w3,acc2[1][3]);
            acc2[2][0]=ffma2(A1.x,w0,acc2[2][0]); acc2[2][1]=ffma2(A1.x,w1,acc2[2][1]);
            acc2[2][2]=ffma2(A1.x,w2,acc2[2][2]); acc2[2][3]=ffma2(A1.x,w3,acc2[2][3]);
            acc2[3][0]=ffma2(A1.y,w0,acc2[3][0]); acc2[3][1]=ffma2(A1.y,w1,acc2[3][1]);
            acc2[3][2]=ffma2(A1.y,w2,acc2[3][2]); acc2[3][3]=ffma2(A1.y,w3,acc2[3][3]);
            acc2[4][0]=ffma2(A2.x,w0,acc2[4][0]); acc2[4][1]=ffma2(A2.x,w1,acc2[4][1]);
            acc2[4][2]=ffma2(A2.x,w2,acc2[4][2]); acc2[4][3]=ffma2(A2.x,w3,acc2[4][3]);
            acc2[5][0]=ffma2(A2.y,w0,acc2[5][0]); acc2[5][1]=ffma2(A2.y,w1,acc2[5][1]);
            acc2[5][2]=ffma2(A2.y,w2,acc2[5][2]); acc2[5][3]=ffma2(A2.y,w3,acc2[5][3]);
            acc2[6][0]=ffma2(A3.x,w0,acc2[6][0]); acc2[6][1]=ffma2(A3.x,w1,acc2[6][1]);
            acc2[6][2]=ffma2(A3.x,w2,acc2[6][2]); acc2[6][3]=ffma2(A3.x,w3,acc2[6][3]);
            acc2[7][0]=ffma2(A3.y,w0,acc2[7][0]); acc2[7][1]=ffma2(A3.y,w1,acc2[7][1]);
            acc2[7][2]=ffma2(A3.y,w2,acc2[7][2]); acc2[7][3]=ffma2(A3.y,w3,acc2[7][3]);
        }
        __syncthreads();
    }

    // relu -> sH
#pragma unroll
    for (int i = 0; i < 8; i++) {
        int r = tm*8 + i;
        float lo, hi;
        upk(acc2[i][0], lo, hi);
        *(ull*)(sH + r*132 + c0)     = pk2(fmaxf(lo,0.f), fmaxf(hi,0.f));
        upk(acc2[i][1], lo, hi);
        *(ull*)(sH + r*132 + c0 + 2) = pk2(fmaxf(lo,0.f), fmaxf(hi,0.f));
        upk(acc2[i][2], lo, hi);
        *(ull*)(sH + r*132 + c1)     = pk2(fmaxf(lo,0.f), fmaxf(hi,0.f));
        upk(acc2[i][3], lo, hi);
        *(ull*)(sH + r*132 + c1 + 2) = pk2(fmaxf(lo,0.f), fmaxf(hi,0.f));
    }
    __syncthreads();

    // phase 2: hm = H @ W2 + b2, sigmoid, scatter (packed heat8)
    const int r   = tid & 127;
    const int grp = tid >> 7;      // 0 -> cls 0..4, 1 -> cls 5..9
    float o[5];
#pragma unroll
    for (int i = 0; i < 5; i++) o[i] = b2[grp*5 + i];
    for (int j = 0; j < 128; j++) {
        float a = sH[r*132 + j];
#pragma unroll
        for (int i = 0; i < 5; i++)
            o[i] = fmaf(a, sW2[j*NCLS + grp*5 + i], o[i]);
    }
    const int gr = rowBase + r;
    const int bi = idxs[gr*3], yi = idxs[gr*3+1], xi = idxs[gr*3+2];
    const int cell = bi*HW + yi*WG + xi;
    if (grp == 0) {
        float4 h4 = make_float4(sigmf(o[0]), sigmf(o[1]), sigmf(o[2]), sigmf(o[3]));
        *(float4*)(g_heat8 + (size_t)cell*8) = h4;
        g_heat8[(size_t)cell*8 + 4] = sigmf(o[4]);
        g_map[cell] = gr;
    } else {
        g_heat8[(size_t)cell*8 + 5] = sigmf(o[0]);   // cls 5
        g_heat8[(size_t)cell*8 + 6] = sigmf(o[1]);   // cls 6
        g_heat8[(size_t)cell*8 + 7] = sigmf(o[2]);   // cls 7
        float s8 = sigmf(o[3]), s9 = sigmf(o[4]);    // cls 8,9: NMS bypass
        g_supp89[gr] = make_float2(s8, s9);
        atomicAdd(&g_hist[bi*NBUCK + (__float_as_uint(s8) >> BSHIFT)], 1u);
        atomicAdd(&g_hist[bi*NBUCK + (__float_as_uint(s9) >> BSHIFT)], 1u);
    }
}

// ---------------- NMS per cell (coalesced) + fused threshold scan -----------
__global__ void nms_kernel() {
    int gid = blockIdx.x * 256 + threadIdx.x;   // over B*HW
    if (gid < BB*HW) {
        const float4* cp = (const float4*)(g_heat8 + (size_t)gid*8);
        float4 cv0 = cp[0], cv1 = cp[1];
        bool occ = (cv0.x!=0.f)|(cv0.y!=0.f)|(cv0.z!=0.f)|(cv0.w!=0.f)
                 | (cv1.x!=0.f)|(cv1.y!=0.f)|(cv1.z!=0.f)|(cv1.w!=0.f);
        int b = (gid >= HW) ? 1 : 0;
        int cell = gid - b*HW;
        int y = cell / WG, x = cell - y*WG;
        bool inner = (y > 0) & (y < HH-1) & (x > 0) & (x < WG-1);
        if (occ & inner) {
            float ctr[8] = {cv0.x, cv0.y, cv0.z, cv0.w, cv1.x, cv1.y, cv1.z, cv1.w};
            float nmx[8] = {0.f,0.f,0.f,0.f,0.f,0.f,0.f,0.f};
            const int offs[8] = {-WG-1, -WG, -WG+1, -1, 1, WG-1, WG, WG+1};
#pragma unroll
            for (int n = 0; n < 8; n++) {
                const float4* q = (const float4*)(g_heat8 + (size_t)(gid + offs[n])*8);
                float4 u0 = q[0], u1 = q[1];
                nmx[0] = fmaxf(nmx[0], u0.x); nmx[1] = fmaxf(nmx[1], u0.y);
                nmx[2] = fmaxf(nmx[2], u0.z); nmx[3] = fmaxf(nmx[3], u0.w);
                nmx[4] = fmaxf(nmx[4], u1.x); nmx[5] = fmaxf(nmx[5], u1.y);
                nmx[6] = fmaxf(nmx[6], u1.z); nmx[7] = fmaxf(nmx[7], u1.w);
            }
            float s[8];
#pragma unroll
            for (int c = 0; c < 8; c++)
                s[c] = (ctr[c] >= nmx[c]) ? ctr[c] : 0.f;
            *(float4*)(g_supp8 + (size_t)gid*8)     = make_float4(s[0],s[1],s[2],s[3]);
            *(float4*)(g_supp8 + (size_t)gid*8 + 4) = make_float4(s[4],s[5],s[6],s[7]);
#pragma unroll
            for (int c = 0; c < 8; c++)
                if (s[c] > 0.f)
                    atomicAdd(&g_hist[b*NBUCK + (__float_as_uint(s[c]) >> BSHIFT)], 1u);
        }
        // border/empty: supp8 stays zero (pre-zeroed)
    }

    // ---- last-block-done: threshold scan (both batches) ----
    __shared__ int isLast;
    __threadfence();
    __syncthreads();
    if (threadIdx.x == 0) {
        unsigned t = atomicAdd(&g_done, 1u);
        isLast = (t == gridDim.x - 1);
    }
    __syncthreads();
    if (!isLast) return;
    __threadfence();

    __shared__ unsigned wtot[8], wexc[8];
    const int t = threadIdx.x;          // 256 threads, 128 buckets each
    const int lane = t & 31, wid = t >> 5;
    for (int b = 0; b < BB; b++) {
        const unsigned* h = g_hist + b*NBUCK;
        const uint4* hv4 = (const uint4*)(h + t*128);
        unsigned v = 0;
#pragma unroll
        for (int i = 0; i < 32; i++) {
            uint4 u = hv4[i];
            v += u.x + u.y + u.z + u.w;
        }
        unsigned s = v;
#pragma unroll
        for (int off = 1; off < 32; off <<= 1) {
            unsigned u = __shfl_down_sync(0xFFFFFFFFu, s, off);
            if (lane + off < 32) s += u;
        }
        if (lane == 0) wtot[wid] = s;
        __syncthreads();
        if (wid == 0 && lane < 8) {
            unsigned ws = wtot[lane];
            unsigned sw = ws;
#pragma unroll
            for (int off = 1; off < 8; off <<= 1) {
                unsigned u = __shfl_down_sync(0xFFu, sw, off);
                if (lane + off < 8) sw += u;
            }
            wexc[lane] = sw - ws;
        }
        __syncthreads();
        unsigned S = s + wexc[wid];
        unsigned Snext = S - v;
        if (S >= NPROP && Snext < NPROP) {
            unsigned acc = Snext;
            int T = t*128;
            bool found = false;
            for (int blk = 31; blk >= 0 && !found; blk--) {
                uint4 u = hv4[blk];
                unsigned e[4] = {u.x, u.y, u.z, u.w};
                for (int i = 3; i >= 0; i--) {
                    if (acc + e[i] >= NPROP) { T = t*128 + blk*4 + i; found = true; break; }
                    acc += e[i];
                }
            }
            g_thr[b] = T;
        }
        __syncthreads();
    }
}

// ---------------- gather: cell sweep (cls 0..7) + point sweep (cls 8,9) -----
__global__ void gather_kernel(const int* __restrict__ idxs) {
    int gid = blockIdx.x * 256 + threadIdx.x;
    if (gid < BB*HW) {
        int b = (gid >= HW) ? 1 : 0;
        int cell = gid - b*HW;
        int T = g_thr[b];
        const float4* sp = (const float4*)(g_supp8 + (size_t)gid*8);
        float4 s0 = sp[0], s1 = sp[1];
        float sv[8] = {s0.x, s0.y, s0.z, s0.w, s1.x, s1.y, s1.z, s1.w};
#pragma unroll
        for (int c = 0; c < 8; c++) {
            unsigned vb = __float_as_uint(sv[c]);
            if (sv[c] > 0.f && (int)(vb >> BSHIFT) >= T) {
                unsigned j = (unsigned)(c*HW + cell);
                ull sk = ((ull)vb << 32) | (ull)(0xFFFFFFFFu - j);
                int p = atomicAdd(&g_selcnt[b], 1);
                if (p < SEL_CAP) g_sel[b*SEL_CAP + p] = sk;
            }
        }
    }
    if (gid < NPTS) {
        int b = idxs[3*gid], y = idxs[3*gid+1], x = idxs[3*gid+2];
        int cell = y*WG + x;
        int T = g_thr[b];
        float2 s89 = g_supp89[gid];
        float sv[2] = {s89.x, s89.y};
#pragma unroll
        for (int i = 0; i < 2; i++) {
            unsigned vb = __float_as_uint(sv[i]);
            if ((int)(vb >> BSHIFT) >= T) {
                unsigned j = (unsigned)((8+i)*HW + cell);
                ull sk = ((ull)vb << 32) | (ull)(0xFFFFFFFFu - j);
                int p = atomicAdd(&g_selcnt[b], 1);
                if (p < SEL_CAP) g_sel[b*SEL_CAP + p] = sk;
            }
        }
    }
}

// ---------------- finalize: exact rank + all outputs (1 block / batch) ------
__global__ void finalize_kernel(const float* __restrict__ feat,
                                const float* __restrict__ Wcls,
                                const float* __restrict__ bcls,
                                float* __restrict__ out)
{
    __shared__ ull ssk[SEL_CAP];
    __shared__ ull stop[NPROP];
    int b = blockIdx.x, tid = threadIdx.x;
    int M = g_selcnt[b]; if (M > SEL_CAP) M = SEL_CAP;
    for (int i = tid; i < M; i += 1024) ssk[i] = g_sel[b*SEL_CAP + i];
    __syncthreads();
    for (int i = tid; i < M; i += 1024) {
        ull v = ssk[i];
        int r = 0;
        for (int j = 0; j < M; j++) r += (ssk[j] > v);
        if (r < NPROP) stop[r] = v;
    }
    __syncthreads();
    // qf: 200 x 128
    for (int e = tid; e < NPROP*CC; e += 1024) {
        int p = e >> 7, c = e & 127;
        unsigned key = 0xFFFFFFFFu - (unsigned)(stop[p] & 0xFFFFFFFFu);
        int cls = key / HW, idx = key - cls*HW;
        int row = g_map[b*HW + idx];
        out[OFF_QF + (b*CC + c)*NPROP + p] =
            feat[(size_t)row*CC + c] + Wcls[c*NCLS + cls] + bcls[c];
    }
    // qhs: 200 x 10
    for (int e = tid; e < NPROP*NCLS; e += 1024) {
        int p = e / NCLS, c = e - p*NCLS;
        unsigned key = 0xFFFFFFFFu - (unsigned)(stop[p] & 0xFFFFFFFFu);
        int cls = key / HW, idx = key - cls*HW;
        float val;
        if (c < 8) {
            val = g_supp8[((size_t)b*HW + idx)*8 + c];
        } else {
            int row = g_map[b*HW + idx];
            float2 s89 = g_supp89[row];
            val = (c == 8) ? s89.x : s89.y;
        }
        out[OFF_QHS + (b*NCLS + c)*NPROP + p] = val;
    }
    // pos + cls
    for (int p = tid; p < NPROP; p += 1024) {
        unsigned key = 0xFFFFFFFFu - (unsigned)(stop[p] & 0xFFFFFFFFu);
        int cls = key / HW, idx = key - cls*HW;
        out[OFF_POS + (b*NPROP + p)*2 + 0] = (float)(idx % WG);
        out[OFF_POS + (b*NPROP + p)*2 + 1] = (float)(idx / WG);
        out[OFF_CLS + b*NPROP + p] = (float)cls;
    }
}

// ---------------- launch ----------------------------------------------------
extern "C" void kernel_launch(void* const* d_in, const int* in_sizes, int n_in,
                              void* d_out, int out_size)
{
    const float* feat = (const float*)d_in[0];
    const float* W1   = (const float*)d_in[1];
    const float* b1   = (const float*)d_in[2];
    const float* W2   = (const float*)d_in[3];
    const float* b2   = (const float*)d_in[4];
    const float* Wcls = (const float*)d_in[5];
    const float* bcls = (const float*)d_in[6];
    const int*   idxs = (const int*)d_in[7];
    float* out = (float*)d_out;

    cudaFuncSetAttribute(gemm_kernel, cudaFuncAttributeMaxDynamicSharedMemorySize,
                         SMEM_FLOATS * (int)sizeof(float));

    init_kernel<<<2048, 256>>>();
    gemm_kernel<<<NPTS/128, 256, SMEM_FLOATS * sizeof(float)>>>(feat, W1, b1, W2, b2, idxs);
    nms_kernel<<<(BB*HW + 255)/256, 256>>>();
    gather_kernel<<<(BB*HW + 255)/256, 256>>>(idxs);
    finalize_kernel<<<BB, 1024>>>(feat, Wcls, bcls, out);
}

// round 13
// speedup vs baseline: 1.1084x; 1.1084x over previous
#include <cuda_runtime.h>
#include <math.h>

#define BB    2
#define HH    360
#define WG    360
#define HW    (HH*WG)          // 129600
#define NCLS  10
#define NPROP 200
#define CC    128
#define NPTS  80000
#define NBUCK 65536            // bucket = float_bits >> 16
#define SEL_CAP 4096

// output layout: qf (B,C,P) | query_pos (B,P,2) | qhs (B,NCLS,P) | cls (B,P)
#define OFF_QF  0
#define OFF_POS (BB*CC*NPROP)            // 51200
#define OFF_QHS (OFF_POS + BB*NPROP*2)   // 52000
#define OFF_CLS (OFF_QHS + BB*NCLS*NPROP)// 56000

typedef unsigned long long ull;

// ---------------- scratch (device globals; re-initialized every launch) ----
__device__ float g_heat[BB*NCLS*HW];     // raw sigmoid heat, dense planar
__device__ float g_supp[BB*NCLS*HW];     // suppressed heat, dense planar
__device__ int   g_map [BB*HW];          // cell -> point row (-1 empty)
__device__ unsigned g_hist[BB*NBUCK];
__device__ int   g_thr[BB];
__device__ int   g_selcnt[BB];
__device__ ull   g_sel[BB*SEL_CAP];
__device__ ull   g_top[BB*NPROP];

// ---------------- packed f32x2 helpers --------------------------------------
__device__ __forceinline__ ull pk2(float lo, float hi) {
    ull r;
    asm("mov.b64 %0, {%1, %2};" : "=l"(r)
        : "r"(__float_as_uint(lo)), "r"(__float_as_uint(hi)));
    return r;
}
__device__ __forceinline__ ull pk1(float v) {
    ull r;
    asm("mov.b64 %0, {%1, %1};" : "=l"(r) : "r"(__float_as_uint(v)));
    return r;
}
__device__ __forceinline__ void upk(ull p, float& lo, float& hi) {
    unsigned a, b;
    asm("mov.b64 {%0, %1}, %2;" : "=r"(a), "=r"(b) : "l"(p));
    lo = __uint_as_float(a); hi = __uint_as_float(b);
}
__device__ __forceinline__ ull ffma2(ull a, ull b, ull c) {
    ull d;
    asm("fma.rn.f32x2 %0, %1, %2, %3;" : "=l"(d) : "l"(a), "l"(b), "l"(c));
    return d;
}

// ---------------- init (3 kernels: puts gemm at launch index 3) -------------
__global__ void initA_kernel() {      // zero g_heat
    int stride = gridDim.x * blockDim.x;
    int i0 = blockIdx.x * blockDim.x + threadIdx.x;
    float4 z4 = make_float4(0.f, 0.f, 0.f, 0.f);
    for (int j = i0; j < BB*NCLS*HW/4; j += stride) ((float4*)g_heat)[j] = z4;
}
__global__ void initB_kernel() {      // zero g_supp
    int stride = gridDim.x * blockDim.x;
    int i0 = blockIdx.x * blockDim.x + threadIdx.x;
    float4 z4 = make_float4(0.f, 0.f, 0.f, 0.f);
    for (int j = i0; j < BB*NCLS*HW/4; j += stride) ((float4*)g_supp)[j] = z4;
}
__global__ void initC_kernel() {      // map=-1, hist=0, counters=0
    int stride = gridDim.x * blockDim.x;
    int i0 = blockIdx.x * blockDim.x + threadIdx.x;
    int4 m4 = make_int4(-1, -1, -1, -1);
    for (int j = i0; j < BB*HW/4; j += stride) ((int4*)g_map)[j] = m4;
    uint4 zu = make_uint4(0u, 0u, 0u, 0u);
    for (int j = i0; j < BB*NBUCK/4; j += stride) ((uint4*)g_hist)[j] = zu;
    if (i0 < BB) g_selcnt[i0] = 0;
}

// ---------------- fused MLP head (exact R6 GEMM) ----------------------------
// block: 256 threads, 128 rows x 128 cols tile; W1 resident in smem.
// dyn smem (floats): [0,16384) W1 | [16384,20608) A(32x132) |
//                    reuse [0,16896) H(128x132) | [20608,21888) W2
#define SMEM_FLOATS 21888
__global__ void __launch_bounds__(256, 2)
gemm_kernel(const float* __restrict__ feat, const float* __restrict__ W1,
            const float* __restrict__ b1,  const float* __restrict__ W2,
            const float* __restrict__ b2,  const int* __restrict__ idxs)
{
    extern __shared__ float sm[];
    float* sW1 = sm;                 // 128*128
    float* sA  = sm + 16384;         // 32*132
    float* sH  = sm;                 // 128*132 (reuses W1+A after phase 1)
    float* sW2 = sm + 20608;         // 128*10

    const int tid = threadIdx.x;
    const int rowBase = blockIdx.x * 128;

    for (int i = tid*4; i < CC*CC; i += 256*4)
        *(float4*)(sW1 + i) = *(const float4*)(W1 + i);
    for (int i = tid; i < CC*NCLS; i += 256)
        sW2[i] = W2[i];

    const int tn = tid & 15, tm = tid >> 4;
    const int c0 = tn*4;          // cols c0..c0+3
    const int c1 = 64 + tn*4;     // cols c1..c1+3

    ull acc2[8][4];
    {
        ull p0 = pk2(b1[c0],   b1[c0+1]);
        ull p1 = pk2(b1[c0+2], b1[c0+3]);
        ull p2 = pk2(b1[c1],   b1[c1+1]);
        ull p3 = pk2(b1[c1+2], b1[c1+3]);
#pragma unroll
        for (int i = 0; i < 8; i++) {
            acc2[i][0] = p0; acc2[i][1] = p1; acc2[i][2] = p2; acc2[i][3] = p3;
        }
    }
    __syncthreads();   // W1/W2 visible

    const int lrow = tid >> 3;          // 0..31
    const int lk4  = (tid & 7) * 4;     // 0..28
    for (int kc = 0; kc < 4; kc++) {
#pragma unroll
        for (int pass = 0; pass < 4; pass++) {
            int r = lrow + pass*32;
            float4 v = *(const float4*)(feat + (size_t)(rowBase + r)*CC + kc*32 + lk4);
            sA[(lk4+0)*132 + r] = v.x;
            sA[(lk4+1)*132 + r] = v.y;
            sA[(lk4+2)*132 + r] = v.z;
            sA[(lk4+3)*132 + r] = v.w;
        }
        __syncthreads();
#pragma unroll 4
        for (int k = 0; k < 32; k++) {
            float a[8];
            *(float4*)(a)    = *(float4*)(sA + k*132 + tm*8);
            *(float4*)(a+4)  = *(float4*)(sA + k*132 + tm*8 + 4);
            const ull* bw = (const ull*)(sW1 + (kc*32+k)*128);
            ull w0 = bw[tn*2];
            ull w1 = bw[tn*2 + 1];
            ull w2 = bw[32 + tn*2];
            ull w3 = bw[32 + tn*2 + 1];
#pragma unroll
            for (int i = 0; i < 8; i++) {
                ull aa = pk1(a[i]);
                acc2[i][0] = ffma2(aa, w0, acc2[i][0]);
                acc2[i][1] = ffma2(aa, w1, acc2[i][1]);
                acc2[i][2] = ffma2(aa, w2, acc2[i][2]);
                acc2[i][3] = ffma2(aa, w3, acc2[i][3]);
            }
        }
        __syncthreads();
    }

    // relu -> sH (packed 8B stores; offsets even -> aligned)
#pragma unroll
    for (int i = 0; i < 8; i++) {
        int r = tm*8 + i;
        float lo, hi;
        upk(acc2[i][0], lo, hi);
        *(ull*)(sH + r*132 + c0)     = pk2(fmaxf(lo,0.f), fmaxf(hi,0.f));
        upk(acc2[i][1], lo, hi);
        *(ull*)(sH + r*132 + c0 + 2) = pk2(fmaxf(lo,0.f), fmaxf(hi,0.f));
        upk(acc2[i][2], lo, hi);
        *(ull*)(sH + r*132 + c1)     = pk2(fmaxf(lo,0.f), fmaxf(hi,0.f));
        upk(acc2[i][3], lo, hi);
        *(ull*)(sH + r*132 + c1 + 2) = pk2(fmaxf(lo,0.f), fmaxf(hi,0.f));
    }
    __syncthreads();

    // phase 2: hm = H @ W2 + b2, sigmoid, scatter (planar heat)
    const int r   = tid & 127;
    const int grp = tid >> 7;      // 0 -> cls 0..4, 1 -> cls 5..9
    float o[5];
#pragma unroll
    for (int i = 0; i < 5; i++) o[i] = b2[grp*5 + i];
    for (int j = 0; j < 128; j++) {
        float a = sH[r*132 + j];
#pragma unroll
        for (int i = 0; i < 5; i++)
            o[i] = fmaf(a, sW2[j*NCLS + grp*5 + i], o[i]);
    }
    const int gr = rowBase + r;
    const int bi = idxs[gr*3], yi = idxs[gr*3+1], xi = idxs[gr*3+2];
    const int cell = yi*WG + xi;
#pragma unroll
    for (int i = 0; i < 5; i++) {
        int c = grp*5 + i;
        float heat = 1.f / (1.f + expf(-o[i]));
        g_heat[(bi*NCLS + c)*HW + cell] = heat;
    }
    if (grp == 0) g_map[bi*HW + cell] = gr;
}

// ---------------- NMS + histogram (exact R6) --------------------------------
__global__ void nms_kernel() {
    int gid = blockIdx.x * blockDim.x + threadIdx.x;   // over B*HW
    if (gid >= BB*HW) return;
    if (g_map[gid] < 0) return;                        // empty cell: supp stays 0
    int b = gid / HW, cell = gid - b*HW;
    int y = cell / WG, x = cell - y*WG;
    bool inner = (y > 0) & (y < HH-1) & (x > 0) & (x < WG-1);
    const float* hb = g_heat + (size_t)b*NCLS*HW;
    for (int c = 0; c < NCLS; c++) {
        const float* hc = hb + c*HW;
        float ctr = hc[cell];
        float s;
        if (c >= 8) {
            s = ctr;
        } else if (!inner) {
            s = 0.f;   // border: local_max==0, heat>0 -> suppressed
        } else {
            bool keep = (ctr >= hc[cell-WG-1]) & (ctr >= hc[cell-WG]) & (ctr >= hc[cell-WG+1])
                      & (ctr >= hc[cell-1])                           & (ctr >= hc[cell+1])
                      & (ctr >= hc[cell+WG-1]) & (ctr >= hc[cell+WG]) & (ctr >= hc[cell+WG+1]);
            s = keep ? ctr : 0.f;
        }
        if (s > 0.f) {
            g_supp[((size_t)b*NCLS + c)*HW + cell] = s;
            atomicAdd(&g_hist[b*NBUCK + (__float_as_uint(s) >> 16)], 1u);
        }
    }
}

// ---------------- threshold bucket of rank-200 (warp-shuffle suffix scan) ---
__global__ void thresh_kernel() {
    __shared__ unsigned wtot[32], wexc[32];
    int b = blockIdx.x;
    const unsigned* h = g_hist + b*NBUCK;
    int t = threadIdx.x;                 // 1024 threads x 64 buckets
    const uint4* hv4 = (const uint4*)(h + t*64);
    unsigned v = 0;
#pragma unroll
    for (int i = 0; i < 16; i++) {
        uint4 u = hv4[i];
        v += u.x + u.y + u.z + u.w;
    }
    int lane = t & 31, wid = t >> 5;
    unsigned s = v;                      // inclusive lane-suffix within warp
#pragma unroll
    for (int off = 1; off < 32; off <<= 1) {
        unsigned u = __shfl_down_sync(0xFFFFFFFFu, s, off);
        if (lane + off < 32) s += u;
    }
    if (lane == 0) wtot[wid] = s;
    __syncthreads();
    if (wid == 0) {
        unsigned ws = wtot[lane];
        unsigned sw = ws;
#pragma unroll
        for (int off = 1; off < 32; off <<= 1) {
            unsigned u = __shfl_down_sync(0xFFFFFFFFu, sw, off);
            if (lane + off < 32) sw += u;
        }
        wexc[lane] = sw - ws;            // strict suffix of warp totals
    }
    __syncthreads();
    unsigned S = s + wexc[wid];          // suffix over all t' >= t
    unsigned Snext = S - v;
    if (S >= NPROP && Snext < NPROP) {   // exactly one thread
        unsigned acc = Snext;
        int T = t*64;
        for (int i = 63; i >= 0; i--) {
            unsigned c = h[t*64 + i];    // L1 hot
            if (acc + c >= NPROP) { T = t*64 + i; break; }
            acc += c;
        }
        g_thr[b] = T;
    }
}

// ---------------- gather candidates >= threshold from DENSE supp (R6) -------
__global__ void gather_kernel() {
    const int N4 = BB*NCLS*HW/4;
    int gid = blockIdx.x * blockDim.x + threadIdx.x;
    if (gid >= N4) return;
    float4 v = ((const float4*)g_supp)[gid];
    int base = gid * 4;
    int b = base / (NCLS*HW);
    int T = g_thr[b];
    float vv[4] = {v.x, v.y, v.z, v.w};
#pragma unroll
    for (int u = 0; u < 4; u++) {
        unsigned vb = __float_as_uint(vv[u]);
        if ((int)(vb >> 16) >= T) {
            unsigned j = (unsigned)(base + u - b*NCLS*HW);   // key = c*HW + cell
            ull sk = ((ull)vb << 32) | (ull)(0xFFFFFFFFu - j);
            int p = atomicAdd(&g_selcnt[b], 1);
            if (p < SEL_CAP) g_sel[b*SEL_CAP + p] = sk;
        }
    }
}

// ---------------- exact rank of the small selected set (R6) -----------------
__global__ void rank_kernel() {
    __shared__ ull sk[SEL_CAP];
    int b = blockIdx.x;
    int M = g_selcnt[b]; if (M > SEL_CAP) M = SEL_CAP;
    for (int i = threadIdx.x; i < M; i += blockDim.x) sk[i] = g_sel[b*SEL_CAP + i];
    __syncthreads();
    for (int i = threadIdx.x; i < M; i += blockDim.x) {
        ull v = sk[i];
        int r = 0;
        for (int j = 0; j < M; j++) r += (sk[j] > v);
        if (r < NPROP) g_top[b*NPROP + r] = v;
    }
}

// ---------------- assemble outputs (R6) -------------------------------------
__global__ void out_kernel(const float* __restrict__ feat,
                           const float* __restrict__ Wcls,
                           const float* __restrict__ bcls,
                           float* __restrict__ out)
{
    int b = blockIdx.x / NPROP, p = blockIdx.x - b*NPROP;
    ull sk = g_top[b*NPROP + p];
    unsigned key = 0xFFFFFFFFu - (unsigned)(sk & 0xFFFFFFFFu);
    int cls = key / HW, idx = key - cls*HW;
    int c = threadIdx.x;
    int row = g_map[b*HW + idx];
    float f = (row >= 0) ? feat[(size_t)row*CC + c] : 0.f;
    out[OFF_QF + (b*CC + c)*NPROP + p] = f + Wcls[c*NCLS + cls] + bcls[c];
    if (c < NCLS)
        out[OFF_QHS + (b*NCLS + c)*NPROP + p] = g_supp[((size_t)b*NCLS + c)*HW + idx];
    if (c == 0) {
        out[OFF_POS + (b*NPROP + p)*2 + 0] = (float)(idx % WG);
        out[OFF_POS + (b*NPROP + p)*2 + 1] = (float)(idx / WG);
        out[OFF_CLS + b*NPROP + p] = (float)cls;
    }
}

// ---------------- launch ----------------------------------------------------
extern "C" void kernel_launch(void* const* d_in, const int* in_sizes, int n_in,
                              void* d_out, int out_size)
{
    const float* feat = (const float*)d_in[0];
    const float* W1   = (const float*)d_in[1];
    const float* b1   = (const float*)d_in[2];
    const float* W2   = (const float*)d_in[3];
    const float* b2   = (const float*)d_in[4];
    const float* Wcls = (const float*)d_in[5];
    const float* bcls = (const float*)d_in[6];
    const int*   idxs = (const int*)d_in[7];
    float* out = (float*)d_out;

    cudaFuncSetAttribute(gemm_kernel, cudaFuncAttributeMaxDynamicSharedMemorySize,
                         SMEM_FLOATS * (int)sizeof(float));

    // launch index 3 == gemm  (profiler captures index 3)
    initA_kernel<<<1024, 256>>>();
    initB_kernel<<<1024, 256>>>();
    initC_kernel<<<512, 256>>>();
    gemm_kernel<<<NPTS/128, 256, SMEM_FLOATS * sizeof(float)>>>(feat, W1, b1, W2, b2, idxs);
    nms_kernel<<<(BB*HW + 255)/256, 256>>>();
    thresh_kernel<<<BB, 1024>>>();
    gather_kernel<<<(BB*NCLS*HW/4 + 255)/256, 256>>>();
    rank_kernel<<<BB, 1024>>>();
    out_kernel<<<BB*NPROP, CC>>>(feat, Wcls, bcls, out);
}